// round 2
// baseline (speedup 1.0000x reference)
#include <cuda_runtime.h>

#define NF 64
#define NH 256
#define NB 8192

typedef unsigned long long u64;

// Separated packed weights (h-contiguous so lane loads are fully coalesced LDG.128):
//   g_wl[f][h] = exp(exu_w[f][h]) * log2(e)   (exp2-domain multiplier for t = e^h)
//   g_wd[f][h] = exp(exu_w[f][h]) * dense_k[f][h]
__device__ float4 g_wl[NF * NH / 4];
__device__ float4 g_wd[NF * NH / 4];
__device__ float g_sumdb;

__global__ void prep_kernel(const float* __restrict__ exu_w,
                            const float* __restrict__ dense_k,
                            const float* __restrict__ dense_b) {
    int i = blockIdx.x * blockDim.x + threadIdx.x;
    if (i < NF * NH) {
        float ew = expf(exu_w[i]);  // accurate exp; prep cost trivial
        reinterpret_cast<float*>(g_wl)[i] = ew * 1.4426950408889634f;
        reinterpret_cast<float*>(g_wd)[i] = ew * dense_k[i];
    }
    if (blockIdx.x == 0 && threadIdx.x < 32) {
        float s = dense_b[threadIdx.x] + dense_b[threadIdx.x + 32];
        #pragma unroll
        for (int o = 16; o > 0; o >>= 1)
            s += __shfl_down_sync(0xffffffffu, s, o);
        if (threadIdx.x == 0) g_sumdb = s;
    }
}

__device__ __forceinline__ float ex2a(float x) {
    float y; asm("ex2.approx.f32 %0, %1;" : "=f"(y) : "f"(x)); return y;
}
__device__ __forceinline__ u64 mul2(u64 a, u64 b) {
    u64 d; asm("mul.rn.f32x2 %0, %1, %2;" : "=l"(d) : "l"(a), "l"(b)); return d;
}
__device__ __forceinline__ u64 add2(u64 a, u64 b) {
    u64 d; asm("add.rn.f32x2 %0, %1, %2;" : "=l"(d) : "l"(a), "l"(b)); return d;
}
__device__ __forceinline__ u64 fma2(u64 a, u64 b, u64 c) {
    u64 d; asm("fma.rn.f32x2 %0, %1, %2, %3;" : "=l"(d) : "l"(a), "l"(b), "l"(c)); return d;
}
__device__ __forceinline__ u64 pack2(float lo, float hi) {
    u64 d; asm("mov.b64 %0, {%1, %2};" : "=l"(d) : "f"(lo), "f"(hi)); return d;
}
__device__ __forceinline__ float2 unpack2(u64 x) {
    float lo, hi; asm("mov.b64 {%0, %1}, %2;" : "=f"(lo), "=f"(hi) : "l"(x));
    return make_float2(lo, hi);
}

// ratio = tanh(softplus(x)) for the packed pair of args (exp2-domain).
// ratio = 1 - 2/v, v = t*(t+2) + 2, t = exp2(arg).
// arg clamped at 60: t <= 2^60 so v <= ~2^120 stays normal/finite, which the
// integer rcp seed + Newton requires (no inf path). Clamp-saturated x gives
// r -> ~2^-121, ratio -> 1 exactly as required.
// 1/v via magic seed + 2 Newton steps: rel err ~ (5e-2)^4 ~ 7e-6.
__device__ __forceinline__ u64 ratio_pair(u64 arg) {
    const u64 TWO2  = 0x4000000040000000ULL;  // ( 2,  2)
    const u64 ONE2  = 0x3F8000003F800000ULL;  // ( 1,  1)
    const u64 NONE2 = 0xBF800000BF800000ULL;  // (-1, -1)
    const u64 NTWO2 = 0xC0000000C0000000ULL;  // (-2, -2)
    float2 a = unpack2(arg);
    float t0 = ex2a(fminf(a.x, 60.0f));
    float t1 = ex2a(fminf(a.y, 60.0f));
    u64 t = pack2(t0, t1);
    u64 v = fma2(t, add2(t, TWO2), TWO2);
    float2 vv = unpack2(v);
    float r0 = __int_as_float(0x7EF311C3 - __float_as_int(vv.x));
    float r1 = __int_as_float(0x7EF311C3 - __float_as_int(vv.y));
    u64 r = pack2(r0, r1);
    r = mul2(r, fma2(mul2(v, r), NONE2, TWO2));   // Newton 1
    r = mul2(r, fma2(mul2(v, r), NONE2, TWO2));   // Newton 2
    return fma2(r, NTWO2, ONE2);                  // 1 - 2r
}

// Block = 256 threads = 8 warps. Warp pair (grp) owns 4 batch rows; half = wid&1
// selects h in [0,128) or [128,256). Lane owns 4 consecutive h's (one ulonglong2
// = 2 f32x2 pairs per weight array) -> perfectly coalesced LDG.128.
// 16 batch rows per block, grid = 512.
__global__ void __launch_bounds__(256, 3)
nam_kernel(const float* __restrict__ X,
           const float* __restrict__ exu_b,
           float* __restrict__ out) {
    const int tid  = threadIdx.x;
    const int lane = tid & 31;
    const int wid  = tid >> 5;
    const int half = wid & 1;
    const int grp  = wid >> 1;                 // 0..3
    const int b0   = blockIdx.x * 16 + grp * 4;
    const int widx = half * 32 + lane;         // ulonglong2 index within f-row (64/f)

    const ulonglong2* wlp = reinterpret_cast<const ulonglong2*>(g_wl);
    const ulonglong2* wdp = reinterpret_cast<const ulonglong2*>(g_wd);

    u64 acc2[4] = {0ULL, 0ULL, 0ULL, 0ULL};

    #pragma unroll 1
    for (int fb = 0; fb < NF; fb += 4) {
        float4 eb  = *reinterpret_cast<const float4*>(exu_b + fb);
        float4 xr0 = *reinterpret_cast<const float4*>(X + (b0 + 0) * NF + fb);
        float4 xr1 = *reinterpret_cast<const float4*>(X + (b0 + 1) * NF + fb);
        float4 xr2 = *reinterpret_cast<const float4*>(X + (b0 + 2) * NF + fb);
        float4 xr3 = *reinterpret_cast<const float4*>(X + (b0 + 3) * NF + fb);

        float dm[4][4];
        dm[0][0] = xr0.x - eb.x; dm[0][1] = xr0.y - eb.y; dm[0][2] = xr0.z - eb.z; dm[0][3] = xr0.w - eb.w;
        dm[1][0] = xr1.x - eb.x; dm[1][1] = xr1.y - eb.y; dm[1][2] = xr1.z - eb.z; dm[1][3] = xr1.w - eb.w;
        dm[2][0] = xr2.x - eb.x; dm[2][1] = xr2.y - eb.y; dm[2][2] = xr2.z - eb.z; dm[2][3] = xr2.w - eb.w;
        dm[3][0] = xr3.x - eb.x; dm[3][1] = xr3.y - eb.y; dm[3][2] = xr3.z - eb.z; dm[3][3] = xr3.w - eb.w;

        #pragma unroll
        for (int j = 0; j < 4; ++j) {
            const int f = fb + j;
            ulonglong2 wl = wlp[f * 64 + widx];
            ulonglong2 wd = wdp[f * 64 + widx];
            #pragma unroll
            for (int r = 0; r < 4; ++r) {
                float d = dm[r][j];
                u64 dd = pack2(d, d);
                u64 w0 = ratio_pair(mul2(dd, wl.x));
                u64 w1 = ratio_pair(mul2(dd, wl.y));
                u64 s  = fma2(wd.y, w1, mul2(wd.x, w0));
                acc2[r] = fma2(dd, s, acc2[r]);   // fold d once per (row,f)
            }
        }
    }

    float accs[4];
    #pragma unroll
    for (int r = 0; r < 4; ++r) {
        float2 u = unpack2(acc2[r]);
        float a = u.x + u.y;
        #pragma unroll
        for (int o = 16; o > 0; o >>= 1)
            a += __shfl_down_sync(0xffffffffu, a, o);
        accs[r] = a;
    }

    __shared__ float sp[8][4];
    if (lane == 0) {
        #pragma unroll
        for (int r = 0; r < 4; ++r) sp[wid][r] = accs[r];
    }
    __syncthreads();
    if (tid < 16) {
        int g = tid >> 2, r = tid & 3;
        out[blockIdx.x * 16 + g * 4 + r] = sp[2 * g][r] + sp[2 * g + 1][r] + g_sumdb;
    }
}

extern "C" void kernel_launch(void* const* d_in, const int* in_sizes, int n_in,
                              void* d_out, int out_size) {
    const float* X       = (const float*)d_in[0];
    const float* exu_w   = (const float*)d_in[1];
    const float* exu_b   = (const float*)d_in[2];
    const float* dense_k = (const float*)d_in[3];
    const float* dense_b = (const float*)d_in[4];
    float* out = (float*)d_out;

    (void)in_sizes; (void)n_in; (void)out_size;

    prep_kernel<<<(NF * NH + 255) / 256, 256>>>(exu_w, dense_k, dense_b);
    nam_kernel<<<NB / 16, 256>>>(X, exu_b, out);
}

// round 3
// speedup vs baseline: 1.2707x; 1.2707x over previous
#include <cuda_runtime.h>

#define NF 64
#define NH 256
#define NB 8192

typedef unsigned long long u64;

// Separated packed weights (h-contiguous, coalesced LDG.128):
//   g_wl[f][h] = exp(exu_w[f][h]) * log2(e)
//   g_wd[f][h] = exp(exu_w[f][h]) * dense_k[f][h]
__device__ float4 g_wl[NF * NH / 4];
__device__ float4 g_wd[NF * NH / 4];
__device__ float g_sumdb;

__global__ void prep_kernel(const float* __restrict__ exu_w,
                            const float* __restrict__ dense_k,
                            const float* __restrict__ dense_b) {
    int i = blockIdx.x * blockDim.x + threadIdx.x;
    if (i < NF * NH) {
        float ew = expf(exu_w[i]);  // accurate exp; prep cost trivial
        reinterpret_cast<float*>(g_wl)[i] = ew * 1.4426950408889634f;
        reinterpret_cast<float*>(g_wd)[i] = ew * dense_k[i];
    }
    if (blockIdx.x == 0 && threadIdx.x < 32) {
        float s = dense_b[threadIdx.x] + dense_b[threadIdx.x + 32];
        #pragma unroll
        for (int o = 16; o > 0; o >>= 1)
            s += __shfl_down_sync(0xffffffffu, s, o);
        if (threadIdx.x == 0) g_sumdb = s;
    }
}

__device__ __forceinline__ float ex2a(float x) {
    float y; asm("ex2.approx.f32 %0, %1;" : "=f"(y) : "f"(x)); return y;
}
__device__ __forceinline__ u64 mul2(u64 a, u64 b) {
    u64 d; asm("mul.rn.f32x2 %0, %1, %2;" : "=l"(d) : "l"(a), "l"(b)); return d;
}
__device__ __forceinline__ u64 add2(u64 a, u64 b) {
    u64 d; asm("add.rn.f32x2 %0, %1, %2;" : "=l"(d) : "l"(a), "l"(b)); return d;
}
__device__ __forceinline__ u64 fma2(u64 a, u64 b, u64 c) {
    u64 d; asm("fma.rn.f32x2 %0, %1, %2, %3;" : "=l"(d) : "l"(a), "l"(b), "l"(c)); return d;
}
__device__ __forceinline__ u64 pack2(float lo, float hi) {
    u64 d; asm("mov.b64 %0, {%1, %2};" : "=l"(d) : "f"(lo), "f"(hi)); return d;
}
__device__ __forceinline__ float2 unpack2(u64 x) {
    float lo, hi; asm("mov.b64 {%0, %1}, %2;" : "=f"(lo), "=f"(hi) : "l"(x));
    return make_float2(lo, hi);
}
__device__ __forceinline__ float rseed(float x) {
    return __int_as_float(0x7EF311C3 - __float_as_int(x));
}

// Block = 256 threads = 8 warps = 4 groups. Group g (warps 2g, 2g+1) owns
// batch rows b0=2g, 2g+1; half = wid&1 selects h in [0,128) or [128,256).
// Lane owns 4 consecutive h's (1 ulonglong2 per weight array per f).
// ratio = tanh(softplus(x)) = 1 - 2/v, v = t(t+2)+2, t = exp2(arg).
// arg clamped at 15: v <= ~2^30, so ratio = 1 - 2^-29 rounds to exactly 1.0f
// (true ratio at arg=15 is 1-1.9e-9), and the shared product P = vA*vB <= 2^60
// stays finite for the integer-seed reciprocal.
// ONE shared 1/(vA*vB) Newton chain per (row,f): r0 = rP*vB, r1 = rP*vA.
__global__ void __launch_bounds__(256, 4)
nam_kernel(const float* __restrict__ X,
           const float* __restrict__ exu_b,
           float* __restrict__ out) {
    const u64 TWO2  = 0x4000000040000000ULL;
    const u64 ONE2  = 0x3F8000003F800000ULL;
    const u64 NTWO2 = 0xC0000000C0000000ULL;
    const u64 SGN2  = 0x8000000080000000ULL;

    const int tid  = threadIdx.x;
    const int lane = tid & 31;
    const int wid  = tid >> 5;            // 0..7
    const int half = wid & 1;
    const int grp  = wid >> 1;            // 0..3
    const int b0   = blockIdx.x * 8 + grp * 2;
    const int widx = half * 32 + lane;    // ulonglong2 index within f-row (64/f)

    const ulonglong2* wlp = reinterpret_cast<const ulonglong2*>(g_wl);
    const ulonglong2* wdp = reinterpret_cast<const ulonglong2*>(g_wd);

    u64 acc2[2] = {0ULL, 0ULL};

    #pragma unroll 1
    for (int fb = 0; fb < NF; fb += 4) {
        float4 eb  = *reinterpret_cast<const float4*>(exu_b + fb);
        float4 xr0 = *reinterpret_cast<const float4*>(X + (b0 + 0) * NF + fb);
        float4 xr1 = *reinterpret_cast<const float4*>(X + (b0 + 1) * NF + fb);

        float dm[2][4];
        dm[0][0] = xr0.x - eb.x; dm[0][1] = xr0.y - eb.y;
        dm[0][2] = xr0.z - eb.z; dm[0][3] = xr0.w - eb.w;
        dm[1][0] = xr1.x - eb.x; dm[1][1] = xr1.y - eb.y;
        dm[1][2] = xr1.z - eb.z; dm[1][3] = xr1.w - eb.w;

        #pragma unroll
        for (int j = 0; j < 4; ++j) {
            const int f = fb + j;
            ulonglong2 wl = wlp[f * 64 + widx];
            ulonglong2 wd = wdp[f * 64 + widx];
            #pragma unroll
            for (int r = 0; r < 2; ++r) {
                float d = dm[r][j];
                u64 dd = pack2(d, d);
                u64 aA = mul2(dd, wl.x);
                u64 aB = mul2(dd, wl.y);
                float2 fA = unpack2(aA);
                float2 fB = unpack2(aB);
                u64 tA = pack2(ex2a(fminf(fA.x, 15.0f)), ex2a(fminf(fA.y, 15.0f)));
                u64 tB = pack2(ex2a(fminf(fB.x, 15.0f)), ex2a(fminf(fB.y, 15.0f)));
                u64 vA = fma2(tA, add2(tA, TWO2), TWO2);
                u64 vB = fma2(tB, add2(tB, TWO2), TWO2);
                u64 P  = mul2(vA, vB);
                float2 pf = unpack2(P);
                u64 rP = pack2(rseed(pf.x), rseed(pf.y));
                u64 nP = P ^ SGN2;
                rP = fma2(rP, fma2(nP, rP, ONE2), rP);   // Newton 1 (2 ops)
                rP = fma2(rP, fma2(nP, rP, ONE2), rP);   // Newton 2 (2 ops)
                u64 w0 = fma2(mul2(rP, vB), NTWO2, ONE2);
                u64 w1 = fma2(mul2(rP, vA), NTWO2, ONE2);
                acc2[r] = fma2(dd, fma2(wd.y, w1, mul2(wd.x, w0)), acc2[r]);
            }
        }
    }

    float accs[2];
    #pragma unroll
    for (int r = 0; r < 2; ++r) {
        float2 u = unpack2(acc2[r]);
        float a = u.x + u.y;
        #pragma unroll
        for (int o = 16; o > 0; o >>= 1)
            a += __shfl_down_sync(0xffffffffu, a, o);
        accs[r] = a;
    }

    __shared__ float sp[8][2];
    if (lane == 0) {
        sp[wid][0] = accs[0];
        sp[wid][1] = accs[1];
    }
    __syncthreads();
    if (tid < 8) {
        int g = tid >> 1, r = tid & 1;
        out[blockIdx.x * 8 + g * 2 + r] = sp[2 * g][r] + sp[2 * g + 1][r] + g_sumdb;
    }
}

extern "C" void kernel_launch(void* const* d_in, const int* in_sizes, int n_in,
                              void* d_out, int out_size) {
    const float* X       = (const float*)d_in[0];
    const float* exu_w   = (const float*)d_in[1];
    const float* exu_b   = (const float*)d_in[2];
    const float* dense_k = (const float*)d_in[3];
    const float* dense_b = (const float*)d_in[4];
    float* out = (float*)d_out;

    (void)in_sizes; (void)n_in; (void)out_size;

    prep_kernel<<<(NF * NH + 255) / 256, 256>>>(exu_w, dense_k, dense_b);
    nam_kernel<<<NB / 8, 256>>>(X, exu_b, out);
}

// round 4
// speedup vs baseline: 1.5612x; 1.2286x over previous
#include <cuda_runtime.h>

#define NF 64
#define NH 256
#define NB 8192

typedef unsigned long long u64;

// Per chain-lane widx (0..63 per f), owning 4 consecutive h = [4w, 4w+3]:
//   g_wl[f*64+w] : packed (exp(exu_w)*log2e) for (h0,h1),(h2,h3)
//   g_w2[f*64+w] : packed 2*exp(exu_w)*dense_k, same pairing
//   g_ws[f*64+w] : packed pair-sums (wd0+wd2, wd1+wd3), wd = exp(exu_w)*dense_k
__device__ float4 g_wl[NF * NH / 4];
__device__ float4 g_w2[NF * NH / 4];
__device__ float2 g_ws[NF * NH / 4];
__device__ float g_sumdb;

__global__ void prep_kernel(const float* __restrict__ exu_w,
                            const float* __restrict__ dense_k,
                            const float* __restrict__ dense_b) {
    int i = blockIdx.x * blockDim.x + threadIdx.x;   // widx global, 4096 total
    if (i < NF * NH / 4) {
        float4 w = *reinterpret_cast<const float4*>(exu_w + 4 * i);
        float4 k = *reinterpret_cast<const float4*>(dense_k + 4 * i);
        float e0 = expf(w.x), e1 = expf(w.y), e2 = expf(w.z), e3 = expf(w.w);
        const float L2E = 1.4426950408889634f;
        g_wl[i] = make_float4(e0 * L2E, e1 * L2E, e2 * L2E, e3 * L2E);
        float d0 = e0 * k.x, d1 = e1 * k.y, d2 = e2 * k.z, d3 = e3 * k.w;
        g_w2[i] = make_float4(2.f * d0, 2.f * d1, 2.f * d2, 2.f * d3);
        g_ws[i] = make_float2(d0 + d2, d1 + d3);
    }
    if (blockIdx.x == 0 && threadIdx.x < 32) {
        float s = dense_b[threadIdx.x] + dense_b[threadIdx.x + 32];
        #pragma unroll
        for (int o = 16; o > 0; o >>= 1)
            s += __shfl_down_sync(0xffffffffu, s, o);
        if (threadIdx.x == 0) g_sumdb = s;
    }
}

__device__ __forceinline__ float ex2a(float x) {
    float y; asm("ex2.approx.f32 %0, %1;" : "=f"(y) : "f"(x)); return y;
}
__device__ __forceinline__ u64 mul2(u64 a, u64 b) {
    u64 d; asm("mul.rn.f32x2 %0, %1, %2;" : "=l"(d) : "l"(a), "l"(b)); return d;
}
__device__ __forceinline__ u64 add2(u64 a, u64 b) {
    u64 d; asm("add.rn.f32x2 %0, %1, %2;" : "=l"(d) : "l"(a), "l"(b)); return d;
}
__device__ __forceinline__ u64 fma2(u64 a, u64 b, u64 c) {
    u64 d; asm("fma.rn.f32x2 %0, %1, %2, %3;" : "=l"(d) : "l"(a), "l"(b), "l"(c)); return d;
}
__device__ __forceinline__ u64 pack2(float lo, float hi) {
    u64 d; asm("mov.b64 %0, {%1, %2};" : "=l"(d) : "f"(lo), "f"(hi)); return d;
}
__device__ __forceinline__ float2 unpack2(u64 x) {
    float lo, hi; asm("mov.b64 {%0, %1}, %2;" : "=f"(lo), "=f"(hi) : "l"(x));
    return make_float2(lo, hi);
}
// seed ~ -1/x directly: bits(-1/x) = 0xFEF311C3 - bits(x) (x positive normal)
__device__ __forceinline__ float nrseed(float x) {
    return __int_as_float((int)(0xFEF311C3u - (unsigned)__float_as_int(x)));
}

// ratio = tanh(softplus(x)) = 1 - 2/v, v = t(t+2)+2, t = exp2(arg), arg = d*wl.
// Clamp arg at 15: v <= ~2^30 (finite for the int-seed rcp), ratio rounds to 1.0f.
// Shared reciprocal: g ~= -1/(vA*vB) via magic seed + ONE cubic (Halley) step
// (eps0^3 ~ 1.3e-4). Per-f contribution per packed lane:
//   wd0*r0 + wd2*r2 = ws + g*(2wd0*vB + 2wd2*vA) = ws + g*m.
// Block = 128 threads = 4 warps = 2 groups; group owns 2 batch rows, wid&1
// picks h-half. Lane owns 4 consecutive h (1 ulonglong2 per array per f).
__global__ void __launch_bounds__(128, 8)
nam_kernel(const float* __restrict__ X,
           const float* __restrict__ exu_b,
           float* __restrict__ out) {
    const u64 TWO2 = 0x4000000040000000ULL;
    const u64 ONE2 = 0x3F8000003F800000ULL;

    const int tid  = threadIdx.x;
    const int lane = tid & 31;
    const int wid  = tid >> 5;            // 0..3
    const int half = wid & 1;
    const int grp  = wid >> 1;            // 0..1
    const int b0   = blockIdx.x * 4 + grp * 2;
    const int widx = half * 32 + lane;    // 0..63 within f-row

    const ulonglong2* wlp = reinterpret_cast<const ulonglong2*>(g_wl);
    const ulonglong2* w2p = reinterpret_cast<const ulonglong2*>(g_w2);
    const u64*        wsp = reinterpret_cast<const u64*>(g_ws);

    u64 acc2[2] = {0ULL, 0ULL};

    #pragma unroll 1
    for (int fb = 0; fb < NF; fb += 4) {
        float4 eb  = *reinterpret_cast<const float4*>(exu_b + fb);
        float4 xr0 = *reinterpret_cast<const float4*>(X + (b0 + 0) * NF + fb);
        float4 xr1 = *reinterpret_cast<const float4*>(X + (b0 + 1) * NF + fb);

        float dm[2][4];
        dm[0][0] = xr0.x - eb.x; dm[0][1] = xr0.y - eb.y;
        dm[0][2] = xr0.z - eb.z; dm[0][3] = xr0.w - eb.w;
        dm[1][0] = xr1.x - eb.x; dm[1][1] = xr1.y - eb.y;
        dm[1][2] = xr1.z - eb.z; dm[1][3] = xr1.w - eb.w;

        #pragma unroll
        for (int j = 0; j < 4; ++j) {
            const int idx = (fb + j) * 64 + widx;
            ulonglong2 wl = wlp[idx];
            ulonglong2 W  = w2p[idx];
            u64        ws = wsp[idx];
            #pragma unroll
            for (int r = 0; r < 2; ++r) {
                float d = dm[r][j];
                u64 dd = pack2(d, d);
                u64 aA = mul2(dd, wl.x);
                u64 aB = mul2(dd, wl.y);
                float2 fA = unpack2(aA);
                float2 fB = unpack2(aB);
                u64 tA = pack2(ex2a(fminf(fA.x, 15.0f)), ex2a(fminf(fA.y, 15.0f)));
                u64 tB = pack2(ex2a(fminf(fB.x, 15.0f)), ex2a(fminf(fB.y, 15.0f)));
                u64 vA = fma2(tA, add2(tA, TWO2), TWO2);
                u64 vB = fma2(tB, add2(tB, TWO2), TWO2);
                u64 P  = mul2(vA, vB);
                float2 pf = unpack2(P);
                u64 g = pack2(nrseed(pf.x), nrseed(pf.y));   // ~ -1/P
                u64 e = fma2(P, g, ONE2);                     // -> 0
                u64 t = fma2(e, e, e);                        // e + e^2
                g = fma2(g, t, g);                            // cubic step
                u64 m = fma2(W.x, vB, mul2(W.y, vA));
                acc2[r] = fma2(dd, fma2(m, g, ws), acc2[r]);
            }
        }
    }

    float accs[2];
    #pragma unroll
    for (int r = 0; r < 2; ++r) {
        float2 u = unpack2(acc2[r]);
        float a = u.x + u.y;
        #pragma unroll
        for (int o = 16; o > 0; o >>= 1)
            a += __shfl_down_sync(0xffffffffu, a, o);
        accs[r] = a;
    }

    __shared__ float sp[4][2];
    if (lane == 0) {
        sp[wid][0] = accs[0];
        sp[wid][1] = accs[1];
    }
    __syncthreads();
    if (tid < 4) {
        int g = tid >> 1, r = tid & 1;
        out[blockIdx.x * 4 + g * 2 + r] = sp[2 * g][r] + sp[2 * g + 1][r] + g_sumdb;
    }
}

extern "C" void kernel_launch(void* const* d_in, const int* in_sizes, int n_in,
                              void* d_out, int out_size) {
    const float* X       = (const float*)d_in[0];
    const float* exu_w   = (const float*)d_in[1];
    const float* exu_b   = (const float*)d_in[2];
    const float* dense_k = (const float*)d_in[3];
    const float* dense_b = (const float*)d_in[4];
    float* out = (float*)d_out;

    (void)in_sizes; (void)n_in; (void)out_size;

    prep_kernel<<<(NF * NH / 4 + 255) / 256, 256>>>(exu_w, dense_k, dense_b);
    nam_kernel<<<NB / 4, 128>>>(X, exu_b, out);
}